// round 8
// baseline (speedup 1.0000x reference)
#include <cuda_runtime.h>
#include <cstdint>
#include <math.h>

#define T  2048
#define HD 1024
#define ID 512
#define NE 32

// ---------------- scratch (device globals: allocation-free) ----------------
__device__ int   g_cnt[NE];
__device__ int   g_tok[NE * T];
__device__ float g_wt [NE * T];
__device__ float g_inter   [(size_t)NE * T * ID];
__device__ float g_inter_sh[(size_t)T * HD];
// raw gate/up outputs (pre-silu)
__device__ float g_rg [(size_t)NE * T * ID];
__device__ float g_ru [(size_t)NE * T * ID];
__device__ float g_rgs[(size_t)T * HD];
__device__ float g_rus[(size_t)T * HD];
// tf32-preconverted operands
__device__ float g_wg [(size_t)NE * ID * HD];
__device__ float g_wu [(size_t)NE * ID * HD];
__device__ float g_wd [(size_t)NE * HD * ID];
__device__ float g_shg[(size_t)2 * ID * HD];
__device__ float g_shu[(size_t)2 * ID * HD];
__device__ float g_shd[(size_t)HD * 2 * ID];
__device__ float g_hc [(size_t)T * HD];

// ---------------- helpers ----------------
__device__ __forceinline__ uint32_t smem_u32(const void* p) {
    uint32_t a;
    asm("{ .reg .u64 t; cvta.to.shared.u64 t, %1; cvt.u32.u64 %0, t; }" : "=r"(a) : "l"(p));
    return a;
}
__device__ __forceinline__ uint32_t to_tf32(float f) {
    uint32_t r;
    asm("cvt.rna.tf32.f32 %0, %1;" : "=r"(r) : "f"(f));
    return r;
}
__device__ __forceinline__ void mma_tf32(float* c, const uint32_t* a, const uint32_t* b) {
    asm volatile(
        "mma.sync.aligned.m16n8k8.row.col.f32.tf32.tf32.f32 "
        "{%0,%1,%2,%3}, {%4,%5,%6,%7}, {%8,%9}, {%0,%1,%2,%3};"
        : "+f"(c[0]), "+f"(c[1]), "+f"(c[2]), "+f"(c[3])
        : "r"(a[0]), "r"(a[1]), "r"(a[2]), "r"(a[3]), "r"(b[0]), "r"(b[1]));
}
__device__ __forceinline__ float silu(float g) {
    return g / (1.f + __expf(-g));
}
#define CP16(dst, src) asm volatile("cp.async.cg.shared.global [%0], [%1], 16;" :: "r"(dst), "l"(src))
#define CP_COMMIT()    asm volatile("cp.async.commit_group;" ::: "memory")
#define CP_WAIT(n)     asm volatile("cp.async.wait_group %0;" :: "n"(n) : "memory")
#define LDSM4(r0, r1, r2, r3, addr) \
    asm volatile("ldmatrix.sync.aligned.m8n8.x4.shared.b16 {%0,%1,%2,%3}, [%4];" \
        : "=r"(r0), "=r"(r1), "=r"(r2), "=r"(r3) : "r"(addr))

// ---------------- tf32 pre-conversion ----------------
__global__ void cvt_tf32_kernel(const float4* __restrict__ src,
                                float4* __restrict__ dst, int n4) {
    int i = blockIdx.x * blockDim.x + threadIdx.x;
    int stride = gridDim.x * blockDim.x;
    for (; i < n4; i += stride) {
        float4 v = src[i];
        float4 o;
        o.x = __uint_as_float(to_tf32(v.x));
        o.y = __uint_as_float(to_tf32(v.y));
        o.z = __uint_as_float(to_tf32(v.z));
        o.w = __uint_as_float(to_tf32(v.w));
        dst[i] = o;
    }
}

// ---------------- zero counters ----------------
__global__ void zero_kernel() {
    if (threadIdx.x < NE) g_cnt[threadIdx.x] = 0;
}

// ---------------- router: 1 warp per token ----------------
__global__ void router_kernel(const float* __restrict__ h,
                              const float* __restrict__ gw,
                              const float* __restrict__ gb) {
    __shared__ float s_sc[4][32];
    __shared__ float s_ss[4][32];
    int wid  = threadIdx.x >> 5;
    int lane = threadIdx.x & 31;
    int t = blockIdx.x * 4 + wid;
    if (t >= T) return;

    const float4* hv = (const float4*)(h + (size_t)t * HD);
    const float4* wv = (const float4*)(gw + (size_t)lane * HD);
    float acc = 0.f;
#pragma unroll 8
    for (int j = 0; j < HD / 4; j++) {
        float4 a = hv[j]; float4 b = wv[j];
        acc += a.x * b.x + a.y * b.y + a.z * b.z + a.w * b.w;
    }
    float score = 1.f / (1.f + expf(-acc));
    s_ss[wid][lane] = score;
    s_sc[wid][lane] = score + gb[lane];
    __syncwarp();

    if (lane == 0) {
        float* SC = s_sc[wid];
        float* SS = s_ss[wid];
        float gs[8];
#pragma unroll
        for (int g = 0; g < 8; g++) {
            float m1 = -1e30f, m2 = -1e30f;
#pragma unroll
            for (int q = 0; q < 4; q++) {
                float v = SC[g * 4 + q];
                if (v > m1) { m2 = m1; m1 = v; }
                else if (v > m2) m2 = v;
            }
            gs[g] = m1 + m2;
        }
        unsigned gsel = 0;
        for (int it = 0; it < 4; it++) {
            float best = -1e30f; int bi = 0;
            for (int g = 0; g < 8; g++)
                if (!((gsel >> g) & 1) && gs[g] > best) { best = gs[g]; bi = g; }
            gsel |= 1u << bi;
        }
        float masked[32];
#pragma unroll
        for (int e = 0; e < 32; e++)
            masked[e] = ((gsel >> (e >> 2)) & 1) ? SC[e] : 0.f;
        int tki[8]; float tw[8];
        unsigned used = 0;
        for (int k = 0; k < 8; k++) {
            float best = -1e30f; int bi = 0;
            for (int e = 0; e < 32; e++)
                if (!((used >> e) & 1) && masked[e] > best) { best = masked[e]; bi = e; }
            used |= 1u << bi;
            tki[k] = bi;
            tw[k] = SS[bi];
        }
        float s = 1e-20f;
        for (int k = 0; k < 8; k++) s += tw[k];
        float inv = 2.5f / s;
        for (int k = 0; k < 8; k++) {
            int e = tki[k];
            int pos = atomicAdd(&g_cnt[e], 1);
            g_tok[e * T + pos] = t;
            g_wt [e * T + pos] = tw[k] * inv;
        }
    }
}

// ============================================================================
// Generic NT GEMM: BM=128, BN=64, BK=32, 256 threads, 3 blocks/SM target.
// 2-stage cp.async ring, ldmatrix fragments, 32 accumulator regs.
// z < NE: routed expert z (gathered A rows, N=512, x<8); z == NE: shared.
// ============================================================================
#define ASTR 36
#define STAGE_W 6912                 // A 4608 + B 2304 words
#define MM_SMEM (2 * STAGE_W * 4)    // 55296 B

// ---- gate or up projection (raw output, no activation) ----
__global__ void __launch_bounds__(256, 3)
mm_nt(const float* __restrict__ h,
      const float* __restrict__ W,  const float* __restrict__ SW,
      float* __restrict__ outR, float* __restrict__ outS)
{
    constexpr int KD = HD;
    constexpr int NT = KD / 32;
    int z = blockIdx.z;
    bool routed = (z < NE);
    if (routed && blockIdx.x >= ID / 64) return;
    int cnt = routed ? g_cnt[z] : T;
    int m0  = blockIdx.y * 128;
    if (m0 >= cnt) return;
    int n0  = blockIdx.x * 64;

    extern __shared__ float smem[];
    uint32_t smem_b = smem_u32(smem);
    __shared__ int s_tok[128];

    int tid  = threadIdx.x;
    int wid  = tid >> 5;
    int lane = tid & 31;
    int wm   = wid & 3;
    int wn   = wid >> 2;

    if (routed && tid < 128) {
        int m = m0 + tid;
        s_tok[tid] = (m < cnt) ? g_tok[z * T + m] : g_tok[z * T];
    }
    __syncthreads();

    const float* B0 = routed ? (W + (size_t)z * ID * HD + (size_t)n0 * KD)
                             : (SW + (size_t)n0 * KD);

    int a_row = tid >> 1;
    int a_c4  = (tid & 1) * 4;
    const float* a_src;
    if (routed) a_src = h + (size_t)s_tok[a_row] * HD;
    else        a_src = h + (size_t)(m0 + a_row) * HD;
    int b_row = tid >> 2;
    int b_c4  = (tid & 3) * 2;
    const float* b_src = B0 + (size_t)b_row * KD;

    uint32_t a_dst = smem_b + (uint32_t)a_row * 144u + (uint32_t)a_c4 * 16u;
    uint32_t b_dst = smem_b + 18432u + (uint32_t)b_row * 144u + (uint32_t)b_c4 * 16u;

#define MM_COPY(st, k0) do { \
    uint32_t off = (uint32_t)(st) * (STAGE_W * 4); \
    const float* ap = a_src + (k0) + a_c4 * 4; \
    const float* bp = b_src + (k0) + b_c4 * 4; \
    CP16(a_dst + off,      ap);      CP16(a_dst + off + 16, ap + 4); \
    CP16(a_dst + off + 32, ap + 8);  CP16(a_dst + off + 48, ap + 12); \
    CP16(b_dst + off,      bp);      CP16(b_dst + off + 16, bp + 4); \
} while (0)

    int lr = lane & 7, lg = lane >> 3;
    uint32_t a_off[2];
#pragma unroll
    for (int mi = 0; mi < 2; mi++) {
        int row = wm * 32 + mi * 16 + (lg & 1) * 8 + lr;
        a_off[mi] = (uint32_t)((row * ASTR + (lg >> 1) * 4) * 4);
    }
    uint32_t bs_off[2];
#pragma unroll
    for (int p = 0; p < 2; p++) {
        int row = wn * 32 + p * 16 + (lg >> 1) * 8 + lr;
        int koff = (lg & 1) * 4;
        bs_off[p] = (uint32_t)((4608 + row * ASTR + koff) * 4);
    }

    float cc[2][4][4] = {};

    MM_COPY(0, 0);
    CP_COMMIT();

    for (int kt = 0; kt < NT; kt++) {
        if (kt + 1 < NT) {
            MM_COPY((kt + 1) & 1, (kt + 1) * 32);
            CP_COMMIT();
            CP_WAIT(1);
        } else {
            CP_WAIT(0);
        }
        __syncthreads();

        uint32_t sb = smem_b + (uint32_t)(kt & 1) * (STAGE_W * 4);
#pragma unroll
        for (int ks = 0; ks < 4; ks++) {
            uint32_t kb = (uint32_t)ks * 32u;
            uint32_t af[2][4];
            LDSM4(af[0][0], af[0][1], af[0][2], af[0][3], sb + a_off[0] + kb);
            LDSM4(af[1][0], af[1][1], af[1][2], af[1][3], sb + a_off[1] + kb);
            uint32_t bf[4][2];
            LDSM4(bf[0][0], bf[0][1], bf[1][0], bf[1][1], sb + bs_off[0] + kb);
            LDSM4(bf[2][0], bf[2][1], bf[3][0], bf[3][1], sb + bs_off[1] + kb);
#pragma unroll
            for (int mi = 0; mi < 2; mi++)
#pragma unroll
                for (int ni = 0; ni < 4; ni++)
                    mma_tf32(cc[mi][ni], af[mi], bf[ni]);
        }
        __syncthreads();
    }
#undef MM_COPY

    int gr = lane >> 2;
    int gc = (lane & 3) * 2;
    int OD = routed ? ID : HD;
    float* obase = routed ? (outR + ((size_t)z * T + m0) * OD)
                          : (outS + (size_t)m0 * OD);

#pragma unroll
    for (int mi = 0; mi < 2; mi++) {
        int mA = wm * 32 + mi * 16 + gr;
        int mB = mA + 8;
        bool vA = (m0 + mA) < cnt;
        bool vB = (m0 + mB) < cnt;
#pragma unroll
        for (int ni = 0; ni < 4; ni++) {
            int n = n0 + wn * 32 + ni * 8 + gc;
            float* c = cc[mi][ni];
            if (vA) *(float2*)(obase + (size_t)mA * OD + n) = make_float2(c[0], c[1]);
            if (vB) *(float2*)(obase + (size_t)mB * OD + n) = make_float2(c[2], c[3]);
        }
    }
}

// ---- silu(g) * u -> inter (tf32-rounded) ----
__global__ void silu_mul_kernel() {
    int z  = blockIdx.z;
    bool routed = (z < NE);
    int cnt = routed ? g_cnt[z] : T;
    int m0 = blockIdx.y * 128;
    if (m0 >= cnt) return;
    int rows = cnt - m0; if (rows > 128) rows = 128;
    int OD = routed ? ID : HD;
    size_t base = routed ? (((size_t)z * T + m0) * OD) : ((size_t)m0 * OD);

    const float4* gp = (const float4*)((routed ? g_rg  : g_rgs) + base);
    const float4* up = (const float4*)((routed ? g_ru  : g_rus) + base);
    float4*       op = (float4*)((routed ? g_inter : g_inter_sh) + base);

    int n4 = rows * (OD / 4);
    for (int i = threadIdx.x; i < n4; i += blockDim.x) {
        float4 g = gp[i];
        float4 u = up[i];
        float4 o;
        o.x = __uint_as_float(to_tf32(silu(g.x) * u.x));
        o.y = __uint_as_float(to_tf32(silu(g.y) * u.y));
        o.z = __uint_as_float(to_tf32(silu(g.z) * u.z));
        o.w = __uint_as_float(to_tf32(silu(g.w) * u.w));
        op[i] = o;
    }
}

// ---- down-proj (merged: z<NE routed KD=512, z==NE shared KD=1024) ----
__global__ void __launch_bounds__(256, 3)
down_mma(const float* __restrict__ Wd, const float* __restrict__ SWd,
         float* __restrict__ out)
{
    int z = blockIdx.z;
    bool routed = (z < NE);
    int KD = routed ? ID : HD;
    int NT = KD / 32;
    int cnt = routed ? g_cnt[z] : T;
    int m0  = blockIdx.y * 128;
    if (m0 >= cnt) return;
    int n0  = blockIdx.x * 64;

    extern __shared__ float smem[];
    uint32_t smem_b = smem_u32(smem);
    __shared__ int   s_tok[128];
    __shared__ float s_w[128];

    int tid  = threadIdx.x;
    int wid  = tid >> 5;
    int lane = tid & 31;
    int wm   = wid & 3;
    int wn   = wid >> 2;

    if (tid < 128) {
        int m = m0 + tid;
        if (routed) {
            s_tok[tid] = (m < cnt) ? g_tok[z * T + m] : 0;
            s_w[tid]   = (m < cnt) ? g_wt [z * T + m] : 0.f;
        } else {
            s_tok[tid] = m;
            s_w[tid]   = 1.f;
        }
    }
    __syncthreads();

    const float* A0 = routed ? (g_inter + ((size_t)z * T + m0) * ID)
                             : (g_inter_sh + (size_t)m0 * HD);
    const float* B0 = routed ? (Wd + (size_t)z * HD * ID + (size_t)n0 * ID)
                             : (SWd + (size_t)n0 * HD);

    int a_row = tid >> 1;
    int a_c4  = (tid & 1) * 4;
    const float* a_src = A0 + (size_t)a_row * KD;
    int b_row = tid >> 2;
    int b_c4  = (tid & 3) * 2;
    const float* b_src = B0 + (size_t)b_row * KD;

    uint32_t a_dst = smem_b + (uint32_t)a_row * 144u + (uint32_t)a_c4 * 16u;
    uint32_t b_dst = smem_b + 18432u + (uint32_t)b_row * 144u + (uint32_t)b_c4 * 16u;

#define DN_COPY(st, k0) do { \
    uint32_t off = (uint32_t)(st) * (STAGE_W * 4); \
    const float* ap = a_src + (k0) + a_c4 * 4; \
    const float* bp = b_src + (k0) + b_c4 * 4; \
    CP16(a_dst + off,      ap);      CP16(a_dst + off + 16, ap + 4); \
    CP16(a_dst + off + 32, ap + 8);  CP16(a_dst + off + 48, ap + 12); \
    CP16(b_dst + off,      bp);      CP16(b_dst + off + 16, bp + 4); \
} while (0)

    int lr = lane & 7, lg = lane >> 3;
    uint32_t a_off[2];
#pragma unroll
    for (int mi = 0; mi < 2; mi++) {
        int row = wm * 32 + mi * 16 + (lg & 1) * 8 + lr;
        a_off[mi] = (uint32_t)((row * ASTR + (lg >> 1) * 4) * 4);
    }
    uint32_t bs_off[2];
#pragma unroll
    for (int p = 0; p < 2; p++) {
        int row = wn * 32 + p * 16 + (lg >> 1) * 8 + lr;
        int koff = (lg & 1) * 4;
        bs_off[p] = (uint32_t)((4608 + row * ASTR + koff) * 4);
    }

    float cc[2][4][4] = {};

    DN_COPY(0, 0);
    CP_COMMIT();

    for (int kt = 0; kt < NT; kt++) {
        if (kt + 1 < NT) {
            DN_COPY((kt + 1) & 1, (kt + 1) * 32);
            CP_COMMIT();
            CP_WAIT(1);
        } else {
            CP_WAIT(0);
        }
        __syncthreads();

        uint32_t sb = smem_b + (uint32_t)(kt & 1) * (STAGE_W * 4);
#pragma unroll
        for (int ks = 0; ks < 4; ks++) {
            uint32_t kb = (uint32_t)ks * 32u;
            uint32_t af[2][4];
            LDSM4(af[0][0], af[0][1], af[0][2], af[0][3], sb + a_off[0] + kb);
            LDSM4(af[1][0], af[1][1], af[1][2], af[1][3], sb + a_off[1] + kb);
            uint32_t bf[4][2];
            LDSM4(bf[0][0], bf[0][1], bf[1][0], bf[1][1], sb + bs_off[0] + kb);
            LDSM4(bf[2][0], bf[2][1], bf[3][0], bf[3][1], sb + bs_off[1] + kb);
#pragma unroll
            for (int mi = 0; mi < 2; mi++)
#pragma unroll
                for (int ni = 0; ni < 4; ni++)
                    mma_tf32(cc[mi][ni], af[mi], bf[ni]);
        }
        __syncthreads();
    }
#undef DN_COPY

    int gr = lane >> 2;
    int gc = (lane & 3) * 2;

#pragma unroll
    for (int mi = 0; mi < 2; mi++) {
        int mA = wm * 32 + mi * 16 + gr;
        int mB = mA + 8;
        bool vA = (m0 + mA) < cnt;
        bool vB = (m0 + mB) < cnt;
#pragma unroll
        for (int ni = 0; ni < 4; ni++) {
            int n = n0 + wn * 32 + ni * 8 + gc;
            float* c = cc[mi][ni];
            if (vA) {
                float w = s_w[mA];
                float* p = out + (size_t)s_tok[mA] * HD + n;
                atomicAdd(p,     c[0] * w);
                atomicAdd(p + 1, c[1] * w);
            }
            if (vB) {
                float w = s_w[mB];
                float* p = out + (size_t)s_tok[mB] * HD + n;
                atomicAdd(p,     c[2] * w);
                atomicAdd(p + 1, c[3] * w);
            }
        }
    }
}

// ---------------- launch ----------------
extern "C" void kernel_launch(void* const* d_in, const int* in_sizes, int n_in,
                              void* d_out, int out_size) {
    const float* h       = (const float*)d_in[0];
    const float* gate_w  = (const float*)d_in[1];
    const float* gate_b  = (const float*)d_in[2];
    const float* w_gate  = (const float*)d_in[3];
    const float* w_up    = (const float*)d_in[4];
    const float* w_down  = (const float*)d_in[5];
    const float* sh_gate = (const float*)d_in[6];
    const float* sh_up   = (const float*)d_in[7];
    const float* sh_down = (const float*)d_in[8];
    float* out = (float*)d_out;

    cudaFuncSetAttribute(mm_nt,    cudaFuncAttributeMaxDynamicSharedMemorySize, MM_SMEM);
    cudaFuncSetAttribute(down_mma, cudaFuncAttributeMaxDynamicSharedMemorySize, MM_SMEM);

    float *p_wg, *p_wu, *p_wd, *p_shg, *p_shu, *p_shd, *p_hc;
    float *p_rg, *p_ru, *p_rgs, *p_rus;
    cudaGetSymbolAddress((void**)&p_wg,  g_wg);
    cudaGetSymbolAddress((void**)&p_wu,  g_wu);
    cudaGetSymbolAddress((void**)&p_wd,  g_wd);
    cudaGetSymbolAddress((void**)&p_shg, g_shg);
    cudaGetSymbolAddress((void**)&p_shu, g_shu);
    cudaGetSymbolAddress((void**)&p_shd, g_shd);
    cudaGetSymbolAddress((void**)&p_hc,  g_hc);
    cudaGetSymbolAddress((void**)&p_rg,  g_rg);
    cudaGetSymbolAddress((void**)&p_ru,  g_ru);
    cudaGetSymbolAddress((void**)&p_rgs, g_rgs);
    cudaGetSymbolAddress((void**)&p_rus, g_rus);

    zero_kernel<<<1, 32>>>();
    router_kernel<<<T / 4, 128>>>(h, gate_w, gate_b);

    const int NW4 = NE * ID * HD / 4;
    const int NS4 = 2 * ID * HD / 4;
    const int NH4 = T * HD / 4;
    cvt_tf32_kernel<<<2048, 256>>>((const float4*)w_gate,  (float4*)p_wg,  NW4);
    cvt_tf32_kernel<<<2048, 256>>>((const float4*)w_up,    (float4*)p_wu,  NW4);
    cvt_tf32_kernel<<<2048, 256>>>((const float4*)w_down,  (float4*)p_wd,  NW4);
    cvt_tf32_kernel<<<512,  256>>>((const float4*)sh_gate, (float4*)p_shg, NS4);
    cvt_tf32_kernel<<<512,  256>>>((const float4*)sh_up,   (float4*)p_shu, NS4);
    cvt_tf32_kernel<<<512,  256>>>((const float4*)sh_down, (float4*)p_shd, NS4);
    cvt_tf32_kernel<<<1024, 256>>>((const float4*)h,       (float4*)p_hc,  NH4);

    cudaMemsetAsync(out, 0, (size_t)out_size * sizeof(float));

    // gate and up projections (merged routed+shared in z)
    mm_nt<<<dim3(16, T / 128, NE + 1), 256, MM_SMEM>>>(p_hc, p_wg, p_shg, p_rg, p_rgs);
    mm_nt<<<dim3(16, T / 128, NE + 1), 256, MM_SMEM>>>(p_hc, p_wu, p_shu, p_ru, p_rus);
    // silu(g)*u -> inter
    silu_mul_kernel<<<dim3(1, T / 128, NE + 1), 256>>>();
    // down-proj accumulates into zeroed out
    down_mma<<<dim3(HD / 64, T / 128, NE + 1), 256, MM_SMEM>>>(p_wd, p_shd, out);
}